// round 1
// baseline (speedup 1.0000x reference)
#include <cuda_runtime.h>
#include <cstdint>

// Problem constants
#define NIMG 256          // B*L
#define CCH  64           // channels
#define HW   32           // height = width
#define IMGSZ (CCH*HW*HW) // 65536 floats per image
#define NODES 256

// Scratch (device globals: allocation-free per harness rules)
__device__ float g_xs[NIMG * IMGSZ];   // aggregated x
__device__ float g_h [NIMG * IMGSZ];   // hidden
__device__ float g_hs[NIMG * IMGSZ];   // aggregated hidden
__device__ int   g_nbr[NODES * 8];
__device__ int   g_cnt[NODES];
__device__ int   g_mode;               // 0=u8 mask, 1=u16, 2=u32/f32

// ---------------------------------------------------------------------------
// Mask dtype detection: structural check (every row of 64 entries has exactly
// 4 nonzero). Checked narrow->wide so we never read past the real buffer.
// ---------------------------------------------------------------------------
__global__ void detect_kernel(const void* m) {
    __shared__ int bad;
    int row = threadIdx.x;              // 256 rows, 256 threads
    if (row == 0) bad = 0;
    __syncthreads();
    {
        const unsigned char* p = (const unsigned char*)m + row * 64;
        int c = 0;
        for (int j = 0; j < 64; j++) c += (p[j] != 0);
        if (c != 4) atomicOr(&bad, 1);
    }
    __syncthreads();
    int ok8 = !bad;
    __syncthreads();
    if (row == 0) bad = 0;
    __syncthreads();
    if (!ok8) {
        const unsigned short* p = (const unsigned short*)m + row * 64;
        int c = 0;
        for (int j = 0; j < 64; j++) c += (p[j] != 0);
        if (c != 4) atomicOr(&bad, 1);
    }
    __syncthreads();
    int ok16 = (!ok8) && (!bad);
    if (row == 0) g_mode = ok8 ? 0 : (ok16 ? 1 : 2);
}

__global__ void build_kernel(const void* m) {
    int row = threadIdx.x;
    if (row >= NODES) return;
    int mode = g_mode;
    int base = (row >> 6) << 6;   // image base of this batch
    int cnt = 0;
    if (mode == 0) {
        const unsigned char* p = (const unsigned char*)m + row * 64;
        for (int j = 0; j < 64; j++)
            if (p[j]) { if (cnt < 8) g_nbr[row * 8 + cnt] = base + j; cnt++; }
    } else if (mode == 1) {
        const unsigned short* p = (const unsigned short*)m + row * 64;
        for (int j = 0; j < 64; j++)
            if (p[j]) { if (cnt < 8) g_nbr[row * 8 + cnt] = base + j; cnt++; }
    } else {
        const unsigned int* p = (const unsigned int*)m + row * 64;
        for (int j = 0; j < 64; j++)
            if (p[j]) { if (cnt < 8) g_nbr[row * 8 + cnt] = base + j; cnt++; }
    }
    g_cnt[row] = cnt;
}

// ---------------------------------------------------------------------------
// Neighbor aggregation: dst[node] = sum over neighbors j of src[j]
// float4 vectorized; src (64 MB) mostly lives in L2 across the 4x reuse.
// ---------------------------------------------------------------------------
__global__ void agg_kernel(const float* __restrict__ src, float* __restrict__ dst) {
    int node = blockIdx.x;
    int cnt = g_cnt[node];
    if (cnt > 8) cnt = 8;
    int i0 = blockIdx.y * blockDim.x + threadIdx.x;
    int stride = gridDim.y * blockDim.x;
    const float4* s4 = (const float4*)src;
    float4* d4 = (float4*)dst;
    int nb[8];
    for (int k = 0; k < cnt; k++) nb[k] = g_nbr[node * 8 + k];
    const int n4 = IMGSZ / 4;
    for (int i = i0; i < n4; i += stride) {
        float4 acc = make_float4(0.f, 0.f, 0.f, 0.f);
        for (int k = 0; k < cnt; k++) {
            float4 v = s4[nb[k] * n4 + i];
            acc.x += v.x; acc.y += v.y; acc.z += v.z; acc.w += v.w;
        }
        d4[node * n4 + i] = acc;
    }
}

// ---------------------------------------------------------------------------
// Implicit-GEMM 3x3 conv, Cin = 64(inA) + 64(inB), Cout = 64, tf32 mma.sync.
// CTA: 1 image x 8 rows (256 pixels), 8 warps; warp = 1 image row, 32px x 64co.
// out = relu(conv(inA,wA) + conv(inB,wB) + bA + cnt*bB [+ resid])
// ---------------------------------------------------------------------------
__device__ __forceinline__ uint32_t f2tf32(float f) {
    uint32_t u;
    asm("cvt.rna.tf32.f32 %0, %1;" : "=r"(u) : "f"(f));
    return u;
}

__device__ __forceinline__ void mma_tf32(float& d0, float& d1, float& d2, float& d3,
                                         uint32_t a0, uint32_t a1, uint32_t a2, uint32_t a3,
                                         uint32_t b0, uint32_t b1) {
    asm volatile(
        "mma.sync.aligned.m16n8k8.row.col.f32.tf32.tf32.f32 "
        "{%0,%1,%2,%3},{%4,%5,%6,%7},{%8,%9},{%0,%1,%2,%3};"
        : "+f"(d0), "+f"(d1), "+f"(d2), "+f"(d3)
        : "r"(a0), "r"(a1), "r"(a2), "r"(a3), "r"(b0), "r"(b1));
}

__global__ __launch_bounds__(256)
void conv_kernel(const float* __restrict__ inA, const float* __restrict__ inB,
                 const float* __restrict__ wA,  const float* __restrict__ wB,
                 const float* __restrict__ bA,  const float* __restrict__ bB,
                 const float* __restrict__ resid, float* __restrict__ out) {
    // patch[c][row][col]: 8ch x 10 rows (8 + halo) x 36 cols (34 used).
    // stride 360 (c) / 36 (row): A-fragment loads are bank-conflict free.
    __shared__ uint32_t patch[8 * 10 * 36];
    // wsm[tap][ci][co], co padded to 72: B-fragment loads conflict-free.
    __shared__ uint32_t wsm[9 * 8 * 72];

    const int n = blockIdx.y;        // image
    const int rb = blockIdx.x;       // row block (8 rows)
    const int tid = threadIdx.x;
    const int w = tid >> 5;          // warp id = local row
    const int lane = tid & 31;
    const int qid = lane >> 2;       // groupID
    const int q = lane & 3;          // threadID in group
    const int y0 = rb * 8;

    float acc[2][8][4];
#pragma unroll
    for (int mt = 0; mt < 2; mt++)
#pragma unroll
        for (int nt = 0; nt < 8; nt++)
#pragma unroll
            for (int r = 0; r < 4; r++) acc[mt][nt][r] = 0.f;

    for (int half = 0; half < 2; half++) {
        const float* inp = half ? inB : inA;
        const float* wg  = half ? wB  : wA;
        for (int cc = 0; cc < 8; cc++) {
            __syncthreads();
            const int cb = cc * 8;
            // load input patch (zero-padded halo), round to tf32 once
            for (int i = tid; i < 8 * 10 * 36; i += 256) {
                int c = i / 360, rem = i % 360;
                int r = rem / 36, col = rem % 36;
                int gy = y0 + r - 1, gx = col - 1;
                float v = 0.f;
                if (gy >= 0 && gy < HW && gx >= 0 && gx < HW)
                    v = inp[((n * CCH + cb + c) * HW + gy) * HW + gx];
                patch[i] = f2tf32(v);
            }
            // load weights for this 8-channel chunk: w[co, ci, ky, kx]
            for (int i = tid; i < 9 * 8 * 64; i += 256) {
                int tap = i >> 9, rem = i & 511;
                int c = rem >> 6, co = rem & 63;
                wsm[tap * 576 + c * 72 + co] =
                    f2tf32(wg[co * 576 + (cb + c) * 9 + tap]);
            }
            __syncthreads();

#pragma unroll
            for (int tap = 0; tap < 9; tap++) {
                const int ty = tap / 3, tx = tap % 3;
                uint32_t bf[16];
#pragma unroll
                for (int nt = 0; nt < 8; nt++) {
                    int co = nt * 8 + qid;
                    bf[2 * nt    ] = wsm[tap * 576 + q * 72 + co];
                    bf[2 * nt + 1] = wsm[tap * 576 + (q + 4) * 72 + co];
                }
#pragma unroll
                for (int mt = 0; mt < 2; mt++) {
                    const int rowoff = (w + ty) * 36;
                    const int xb = mt * 16 + qid + tx;
                    uint32_t a0 = patch[q * 360 + rowoff + xb];
                    uint32_t a1 = patch[q * 360 + rowoff + xb + 8];
                    uint32_t a2 = patch[(q + 4) * 360 + rowoff + xb];
                    uint32_t a3 = patch[(q + 4) * 360 + rowoff + xb + 8];
#pragma unroll
                    for (int nt = 0; nt < 8; nt++)
                        mma_tf32(acc[mt][nt][0], acc[mt][nt][1],
                                 acc[mt][nt][2], acc[mt][nt][3],
                                 a0, a1, a2, a3, bf[2 * nt], bf[2 * nt + 1]);
                }
            }
        }
    }

    // epilogue: bias (bA + cnt*bB), optional residual, relu
    const int gy = y0 + w;
    const float cntf = (float)g_cnt[n];
#pragma unroll
    for (int nt = 0; nt < 8; nt++) {
        const int co = nt * 8 + 2 * q;
        const float bias0 = bA[co]     + cntf * bB[co];
        const float bias1 = bA[co + 1] + cntf * bB[co + 1];
#pragma unroll
        for (int mt = 0; mt < 2; mt++) {
            const int xa = mt * 16 + qid;
            const int xc = xa + 8;
            const int o0 = ((n * CCH + co) * HW + gy) * HW;
            float v0 = acc[mt][nt][0] + bias0;   // (xa, co)
            float v1 = acc[mt][nt][1] + bias1;   // (xa, co+1)
            float v2 = acc[mt][nt][2] + bias0;   // (xc, co)
            float v3 = acc[mt][nt][3] + bias1;   // (xc, co+1)
            if (resid) {
                v0 += resid[o0 + xa];
                v1 += resid[o0 + 1024 + xa];
                v2 += resid[o0 + xc];
                v3 += resid[o0 + 1024 + xc];
            }
            out[o0 + xa]        = fmaxf(v0, 0.f);
            out[o0 + 1024 + xa] = fmaxf(v1, 0.f);
            out[o0 + xc]        = fmaxf(v2, 0.f);
            out[o0 + 1024 + xc] = fmaxf(v3, 0.f);
        }
    }
}

// ---------------------------------------------------------------------------
extern "C" void kernel_launch(void* const* d_in, const int* in_sizes, int n_in,
                              void* d_out, int out_size) {
    const float* x    = (const float*)d_in[0];
    const float* w_x0 = (const float*)d_in[1];
    const float* b_x0 = (const float*)d_in[2];
    const float* w_n0 = (const float*)d_in[3];
    const float* b_n0 = (const float*)d_in[4];
    const float* w_x1 = (const float*)d_in[5];
    const float* b_x1 = (const float*)d_in[6];
    const float* w_n1 = (const float*)d_in[7];
    const float* b_n1 = (const float*)d_in[8];
    const void*  msk  = d_in[9];
    float* out = (float*)d_out;

    float *xs, *h, *hs;
    cudaGetSymbolAddress((void**)&xs, g_xs);
    cudaGetSymbolAddress((void**)&h,  g_h);
    cudaGetSymbolAddress((void**)&hs, g_hs);

    detect_kernel<<<1, 256>>>(msk);
    build_kernel<<<1, 256>>>(msk);

    dim3 agrid(NODES, 16);
    dim3 cgrid(4, NIMG);

    // layer 1: xs = nbsum(x); h = relu(conv(x,w_x0)+conv(xs,w_n0)+b_x0+cnt*b_n0)
    agg_kernel<<<agrid, 256>>>(x, xs);
    conv_kernel<<<cgrid, 256>>>(x, xs, w_x0, w_n0, b_x0, b_n0, nullptr, h);

    // layer 2: hs = nbsum(h); out = relu(conv(h,w_x1)+conv(hs,w_n1)+bias + x)
    agg_kernel<<<agrid, 256>>>(h, hs);
    conv_kernel<<<cgrid, 256>>>(h, hs, w_x1, w_n1, b_x1, b_n1, x, out);
}

// round 2
// speedup vs baseline: 1.5715x; 1.5715x over previous
#include <cuda_runtime.h>
#include <cstdint>

// Problem constants
#define NIMG 256          // B*L
#define CCH  64           // channels
#define HW   32           // height = width
#define IMGSZ (CCH*HW*HW) // 65536 floats per image
#define NODES 256

// Scratch (device globals: allocation-free per harness rules)
__device__ float g_xs[NIMG * IMGSZ];   // aggregated x
__device__ float g_h [NIMG * IMGSZ];   // hidden
__device__ float g_hs[NIMG * IMGSZ];   // aggregated hidden
__device__ int   g_nbr[NODES * 8];
__device__ int   g_cnt[NODES];
__device__ int   g_mode;               // 0=u8 mask, 1=u16, 2=u32/f32

// Pre-transformed weights, tf32 bits, final smem layout:
// [layer2][half2][cc8][tap9][q4][co68] as uint2 pairs (w[ci=cb+q], w[ci=cb+q+4])
#define WPREP_TOTAL (2*2*8*9*4*68)     // 78336 uint2
__device__ uint2 g_wprep[WPREP_TOTAL];

// patch pair layout constants (uint2 elements)
#define P_ROWS   28      // col pairs per row (cols 0..27; fragments use <=25)
#define P_CSTR   292     // channel stride (10*28 + 12 pad) -> 2*292 mod 32 == 8
#define P_ELEMS  2336    // 8 channels * 292
#define P_FILL   2240    // 8 * 10 * 28 filled entries
#define W_QSTR   68      // co-padded q stride -> 2*68*... bank-phase friendly
#define W_TSTR   272     // 4*68 per tap
#define W_ELEMS  2448    // 9*272 per chunk
#define SMEM_BYTES ((2*P_ELEMS + 2*W_ELEMS) * 8)

__device__ __forceinline__ uint32_t f2tf32(float f) {
    uint32_t u;
    asm("cvt.rna.tf32.f32 %0, %1;" : "=r"(u) : "f"(f));
    return u;
}

__device__ __forceinline__ void cp16(void* s, const void* g) {
    uint32_t sa = (uint32_t)__cvta_generic_to_shared(s);
    asm volatile("cp.async.cg.shared.global [%0], [%1], 16;" :: "r"(sa), "l"(g));
}

__device__ __forceinline__ void mma_tf32(float& d0, float& d1, float& d2, float& d3,
                                         uint32_t a0, uint32_t a1, uint32_t a2, uint32_t a3,
                                         uint32_t b0, uint32_t b1) {
    asm volatile(
        "mma.sync.aligned.m16n8k8.row.col.f32.tf32.tf32.f32 "
        "{%0,%1,%2,%3},{%4,%5,%6,%7},{%8,%9},{%0,%1,%2,%3};"
        : "+f"(d0), "+f"(d1), "+f"(d2), "+f"(d3)
        : "r"(a0), "r"(a1), "r"(a2), "r"(a3), "r"(b0), "r"(b1));
}

// ---------------------------------------------------------------------------
// Mask dtype detection + neighbor list build (unchanged from R1, correct)
// ---------------------------------------------------------------------------
__global__ void detect_kernel(const void* m) {
    __shared__ int bad;
    int row = threadIdx.x;
    if (row == 0) bad = 0;
    __syncthreads();
    {
        const unsigned char* p = (const unsigned char*)m + row * 64;
        int c = 0;
        for (int j = 0; j < 64; j++) c += (p[j] != 0);
        if (c != 4) atomicOr(&bad, 1);
    }
    __syncthreads();
    int ok8 = !bad;
    __syncthreads();
    if (row == 0) bad = 0;
    __syncthreads();
    if (!ok8) {
        const unsigned short* p = (const unsigned short*)m + row * 64;
        int c = 0;
        for (int j = 0; j < 64; j++) c += (p[j] != 0);
        if (c != 4) atomicOr(&bad, 1);
    }
    __syncthreads();
    int ok16 = (!ok8) && (!bad);
    if (row == 0) g_mode = ok8 ? 0 : (ok16 ? 1 : 2);
}

__global__ void build_kernel(const void* m) {
    int row = threadIdx.x;
    if (row >= NODES) return;
    int mode = g_mode;
    int base = (row >> 6) << 6;
    int cnt = 0;
    if (mode == 0) {
        const unsigned char* p = (const unsigned char*)m + row * 64;
        for (int j = 0; j < 64; j++)
            if (p[j]) { if (cnt < 8) g_nbr[row * 8 + cnt] = base + j; cnt++; }
    } else if (mode == 1) {
        const unsigned short* p = (const unsigned short*)m + row * 64;
        for (int j = 0; j < 64; j++)
            if (p[j]) { if (cnt < 8) g_nbr[row * 8 + cnt] = base + j; cnt++; }
    } else {
        const unsigned int* p = (const unsigned int*)m + row * 64;
        for (int j = 0; j < 64; j++)
            if (p[j]) { if (cnt < 8) g_nbr[row * 8 + cnt] = base + j; cnt++; }
    }
    g_cnt[row] = cnt;
}

// ---------------------------------------------------------------------------
// Weight pre-transform: tf32 bits, paired (q, q+4), padded co stride 68.
// ---------------------------------------------------------------------------
__global__ void prep_weights(const float* __restrict__ w_x0, const float* __restrict__ w_n0,
                             const float* __restrict__ w_x1, const float* __restrict__ w_n1) {
    int e = blockIdx.x * 256 + threadIdx.x;
    if (e >= WPREP_TOTAL) return;
    int co = e % 68; int t = e / 68;
    int q   = t & 3;  t >>= 2;
    int tap = t % 9;  t /= 9;
    int cc  = t & 7;  t >>= 3;
    int half = t & 1; int layer = t >> 1;
    const float* w = layer ? (half ? w_n1 : w_x1) : (half ? w_n0 : w_x0);
    uint2 v = make_uint2(0u, 0u);
    if (co < 64) {
        int cb = cc * 8;
        v.x = f2tf32(w[co * 576 + (cb + q) * 9 + tap]);
        v.y = f2tf32(w[co * 576 + (cb + q + 4) * 9 + tap]);
    }
    g_wprep[e] = v;
}

// ---------------------------------------------------------------------------
// Neighbor aggregation (unchanged)
// ---------------------------------------------------------------------------
__global__ void agg_kernel(const float* __restrict__ src, float* __restrict__ dst) {
    int node = blockIdx.x;
    int cnt = g_cnt[node];
    if (cnt > 8) cnt = 8;
    int i0 = blockIdx.y * blockDim.x + threadIdx.x;
    int stride = gridDim.y * blockDim.x;
    const float4* s4 = (const float4*)src;
    float4* d4 = (float4*)dst;
    int nb[8];
    for (int k = 0; k < cnt; k++) nb[k] = g_nbr[node * 8 + k];
    const int n4 = IMGSZ / 4;
    for (int i = i0; i < n4; i += stride) {
        float4 acc = make_float4(0.f, 0.f, 0.f, 0.f);
        for (int k = 0; k < cnt; k++) {
            float4 v = s4[nb[k] * n4 + i];
            acc.x += v.x; acc.y += v.y; acc.z += v.z; acc.w += v.w;
        }
        d4[node * n4 + i] = acc;
    }
}

// ---------------------------------------------------------------------------
// Conv: implicit GEMM, paired 64-bit fragment LDS, cp.async weights,
// software-pipelined chunk loop, 1 barrier per chunk.
// ---------------------------------------------------------------------------
__device__ __forceinline__ void ldg_patch(const float* __restrict__ inp, int n, int cb,
                                          int y0, int tid, float (&v0)[9], float (&v1)[9]) {
#pragma unroll
    for (int k = 0; k < 9; k++) {
        int i = tid + k * 256;
        float a = 0.f, b = 0.f;
        if (i < P_FILL) {
            int c = i / 280, rem = i % 280;
            int r = rem / P_ROWS, col = rem % P_ROWS;
            int gy = y0 + r - 1;
            if (gy >= 0 && gy < HW) {
                const float* row = inp + ((n * CCH + cb + c) * HW + gy) * HW;
                int gx0 = col - 1;
                if (gx0 >= 0) a = row[gx0];
                int gx1 = col + 7;
                if (gx1 < HW) b = row[gx1];
            }
        }
        v0[k] = a; v1[k] = b;
    }
}

__device__ __forceinline__ void sts_patch(uint2* __restrict__ pat, int tid,
                                          const float (&v0)[9], const float (&v1)[9]) {
#pragma unroll
    for (int k = 0; k < 9; k++) {
        int i = tid + k * 256;
        if (i < P_FILL) {
            int c = i / 280, rem = i % 280;
            int r = rem / P_ROWS, col = rem % P_ROWS;
            pat[c * P_CSTR + r * P_ROWS + col] = make_uint2(f2tf32(v0[k]), f2tf32(v1[k]));
        }
    }
}

__global__ __launch_bounds__(256, 2)
void conv_kernel(const float* __restrict__ inA, const float* __restrict__ inB,
                 const uint2* __restrict__ wprep,   // this layer's 16*W_ELEMS block
                 const float* __restrict__ bA,  const float* __restrict__ bB,
                 const float* __restrict__ resid, float* __restrict__ out) {
    extern __shared__ uint8_t smem[];
    uint2* patchB[2];
    patchB[0] = (uint2*)smem;
    patchB[1] = patchB[0] + P_ELEMS;
    uint2* wsmB[2];
    wsmB[0] = patchB[1] + P_ELEMS;
    wsmB[1] = wsmB[0] + W_ELEMS;

    const int n = blockIdx.y;        // image
    const int rb = blockIdx.x;       // row block (8 rows)
    const int tid = threadIdx.x;
    const int w = tid >> 5;          // warp id = local row
    const int lane = tid & 31;
    const int qid = lane >> 2;       // groupID
    const int q = lane & 3;          // threadID in group
    const int y0 = rb * 8;

    float acc[2][8][4];
#pragma unroll
    for (int mt = 0; mt < 2; mt++)
#pragma unroll
        for (int nt = 0; nt < 8; nt++)
#pragma unroll
            for (int r = 0; r < 4; r++) acc[mt][nt][r] = 0.f;

    float v0[9], v1[9];

    // ---- prolog: chunk 0 (half 0, cb 0) ----
    {
#pragma unroll
        for (int k = 0; k < 5; k++) {
            int idx = tid + k * 256;
            if (idx < W_ELEMS / 2)
                cp16(((uint4*)wsmB[0]) + idx, ((const uint4*)wprep) + idx);
        }
        ldg_patch(inA, n, 0, y0, tid, v0, v1);
        sts_patch(patchB[0], tid, v0, v1);
        asm volatile("cp.async.wait_all;" ::: "memory");
        __syncthreads();
    }

    for (int it = 0; it < 16; ++it) {
        const int p = it & 1;
        if (it < 15) {
            const int jt = it + 1;
            const int half = jt >> 3;
            const int cb = (jt & 7) * 8;
            const uint2* src = wprep + jt * W_ELEMS;
            uint2* dstW = wsmB[1 - p];
#pragma unroll
            for (int k = 0; k < 5; k++) {
                int idx = tid + k * 256;
                if (idx < W_ELEMS / 2)
                    cp16(((uint4*)dstW) + idx, ((const uint4*)src) + idx);
            }
            ldg_patch(half ? inB : inA, n, cb, y0, tid, v0, v1);
        }

        // ---- compute chunk it ----
        {
            const uint2* __restrict__ pat = patchB[p];
            const uint2* __restrict__ wq = wsmB[p];
#pragma unroll
            for (int tap = 0; tap < 9; tap++) {
                const int ty = tap / 3, tx = tap % 3;
                uint2 bp[8];
                const uint2* wt = wq + tap * W_TSTR + q * W_QSTR;
#pragma unroll
                for (int nt = 0; nt < 8; nt++) bp[nt] = wt[nt * 8 + qid];
                const int ro = (w + ty) * P_ROWS;
#pragma unroll
                for (int mt = 0; mt < 2; mt++) {
                    const int xb = mt * 16 + qid + tx;
                    uint2 alo = pat[q * P_CSTR + ro + xb];
                    uint2 ahi = pat[(q + 4) * P_CSTR + ro + xb];
#pragma unroll
                    for (int nt = 0; nt < 8; nt++)
                        mma_tf32(acc[mt][nt][0], acc[mt][nt][1],
                                 acc[mt][nt][2], acc[mt][nt][3],
                                 alo.x, alo.y, ahi.x, ahi.y, bp[nt].x, bp[nt].y);
                }
            }
        }

        if (it < 15) sts_patch(patchB[1 - p], tid, v0, v1);
        asm volatile("cp.async.wait_all;" ::: "memory");
        __syncthreads();
    }

    // ---- epilogue ----
    const int gy = y0 + w;
    const float cntf = (float)g_cnt[n];
#pragma unroll
    for (int nt = 0; nt < 8; nt++) {
        const int co = nt * 8 + 2 * q;
        const float bias0 = bA[co]     + cntf * bB[co];
        const float bias1 = bA[co + 1] + cntf * bB[co + 1];
#pragma unroll
        for (int mt = 0; mt < 2; mt++) {
            const int xa = mt * 16 + qid;
            const int xc = xa + 8;
            const int o0 = ((n * CCH + co) * HW + gy) * HW;
            float r0 = acc[mt][nt][0] + bias0;
            float r1 = acc[mt][nt][1] + bias1;
            float r2 = acc[mt][nt][2] + bias0;
            float r3 = acc[mt][nt][3] + bias1;
            if (resid) {
                r0 += resid[o0 + xa];
                r1 += resid[o0 + 1024 + xa];
                r2 += resid[o0 + xc];
                r3 += resid[o0 + 1024 + xc];
            }
            out[o0 + xa]        = fmaxf(r0, 0.f);
            out[o0 + 1024 + xa] = fmaxf(r1, 0.f);
            out[o0 + xc]        = fmaxf(r2, 0.f);
            out[o0 + 1024 + xc] = fmaxf(r3, 0.f);
        }
    }
}

// ---------------------------------------------------------------------------
extern "C" void kernel_launch(void* const* d_in, const int* in_sizes, int n_in,
                              void* d_out, int out_size) {
    const float* x    = (const float*)d_in[0];
    const float* w_x0 = (const float*)d_in[1];
    const float* b_x0 = (const float*)d_in[2];
    const float* w_n0 = (const float*)d_in[3];
    const float* b_n0 = (const float*)d_in[4];
    const float* w_x1 = (const float*)d_in[5];
    const float* b_x1 = (const float*)d_in[6];
    const float* w_n1 = (const float*)d_in[7];
    const float* b_n1 = (const float*)d_in[8];
    const void*  msk  = d_in[9];
    float* out = (float*)d_out;

    float *xs, *h, *hs;
    uint2* wprep;
    cudaGetSymbolAddress((void**)&xs, g_xs);
    cudaGetSymbolAddress((void**)&h,  g_h);
    cudaGetSymbolAddress((void**)&hs, g_hs);
    cudaGetSymbolAddress((void**)&wprep, g_wprep);

    static bool attr_set = false;
    if (!attr_set) {
        cudaFuncSetAttribute(conv_kernel, cudaFuncAttributeMaxDynamicSharedMemorySize,
                             SMEM_BYTES);
        attr_set = true;
    }

    detect_kernel<<<1, 256>>>(msk);
    build_kernel<<<1, 256>>>(msk);
    prep_weights<<<(WPREP_TOTAL + 255) / 256, 256>>>(w_x0, w_n0, w_x1, w_n1);

    dim3 agrid(NODES, 16);
    dim3 cgrid(4, NIMG);
    const int lstride = 16 * W_ELEMS;   // uint2 per layer

    // layer 1
    agg_kernel<<<agrid, 256>>>(x, xs);
    conv_kernel<<<cgrid, 256, SMEM_BYTES>>>(x, xs, wprep, b_x0, b_n0, nullptr, h);

    // layer 2
    agg_kernel<<<agrid, 256>>>(h, hs);
    conv_kernel<<<cgrid, 256, SMEM_BYTES>>>(h, hs, wprep + lstride, b_x1, b_n1, x, out);
}

// round 4
// speedup vs baseline: 2.5016x; 1.5918x over previous
#include <cuda_runtime.h>
#include <cstdint>

// Problem constants
#define NIMG 256          // B*L
#define CCH  64           // channels
#define HW   32           // height = width
#define IMGSZ (CCH*HW*HW) // 65536 floats per image
#define NODES 256

// Scratch (device globals: allocation-free per harness rules)
__device__ float g_xs[NIMG * IMGSZ];   // aggregated x
__device__ float g_h [NIMG * IMGSZ];   // hidden
__device__ float g_hs[NIMG * IMGSZ];   // aggregated hidden
__device__ int   g_nbr[NODES * 8];
__device__ int   g_cnt[NODES];
__device__ int   g_mode;               // 0=u8 mask, 1=u16, 2=u32/f32

// Pre-transformed weights, tf32 bits:
// [chunk32 = layer*16 + half*8 + cc][tap9][qid8][q4][nt pad 10] uint2
// pair = (w[ci=cb+q][co], w[ci=cb+q+4][co]), co = nt*8+qid
#define W_CHUNK  2880                  // uint2 per chunk (9*8*4*10)
#define W_TAP_U4 160                   // uint4 per tap block (8*4*10/2)
#define WPREP_TOTAL (32 * W_CHUNK)
__device__ uint2 g_wprep[WPREP_TOTAL];

// patch layout: [c8][row10][36 floats]; word col 1+gx; halo cols stay zero
#define P_CSTR 360      // channel stride (10*36) -> mod 32 == 8, conflict-free
#define P_RSTR 36
#define P_ELEMS 2880    // floats per buffer
#define SMEM_BYTES (2*P_ELEMS*4 + 2*W_CHUNK*8)   // 23040 + 46080 = 69120

__device__ __forceinline__ uint32_t f2tf32(float f) {
    uint32_t u;
    asm("cvt.rna.tf32.f32 %0, %1;" : "=r"(u) : "f"(f));
    return u;
}

__device__ __forceinline__ void cp16(void* s, const void* g) {
    uint32_t sa = (uint32_t)__cvta_generic_to_shared(s);
    asm volatile("cp.async.cg.shared.global [%0], [%1], 16;" :: "r"(sa), "l"(g));
}

__device__ __forceinline__ void cp4(void* s, const void* g) {
    uint32_t sa = (uint32_t)__cvta_generic_to_shared(s);
    asm volatile("cp.async.ca.shared.global [%0], [%1], 4;" :: "r"(sa), "l"(g));
}

__device__ __forceinline__ void mma_tf32(float& d0, float& d1, float& d2, float& d3,
                                         uint32_t a0, uint32_t a1, uint32_t a2, uint32_t a3,
                                         uint32_t b0, uint32_t b1) {
    asm volatile(
        "mma.sync.aligned.m16n8k8.row.col.f32.tf32.tf32.f32 "
        "{%0,%1,%2,%3},{%4,%5,%6,%7},{%8,%9},{%0,%1,%2,%3};"
        : "+f"(d0), "+f"(d1), "+f"(d2), "+f"(d3)
        : "r"(a0), "r"(a1), "r"(a2), "r"(a3), "r"(b0), "r"(b1));
}

// ---------------------------------------------------------------------------
// Mask dtype detection + neighbor list build (unchanged, correct)
// ---------------------------------------------------------------------------
__global__ void detect_kernel(const void* m) {
    __shared__ int bad;
    int row = threadIdx.x;
    if (row == 0) bad = 0;
    __syncthreads();
    {
        const unsigned char* p = (const unsigned char*)m + row * 64;
        int c = 0;
        for (int j = 0; j < 64; j++) c += (p[j] != 0);
        if (c != 4) atomicOr(&bad, 1);
    }
    __syncthreads();
    int ok8 = !bad;
    __syncthreads();
    if (row == 0) bad = 0;
    __syncthreads();
    if (!ok8) {
        const unsigned short* p = (const unsigned short*)m + row * 64;
        int c = 0;
        for (int j = 0; j < 64; j++) c += (p[j] != 0);
        if (c != 4) atomicOr(&bad, 1);
    }
    __syncthreads();
    int ok16 = (!ok8) && (!bad);
    if (row == 0) g_mode = ok8 ? 0 : (ok16 ? 1 : 2);
}

__global__ void build_kernel(const void* m) {
    int row = threadIdx.x;
    if (row >= NODES) return;
    int mode = g_mode;
    int base = (row >> 6) << 6;
    int cnt = 0;
    if (mode == 0) {
        const unsigned char* p = (const unsigned char*)m + row * 64;
        for (int j = 0; j < 64; j++)
            if (p[j]) { if (cnt < 8) g_nbr[row * 8 + cnt] = base + j; cnt++; }
    } else if (mode == 1) {
        const unsigned short* p = (const unsigned short*)m + row * 64;
        for (int j = 0; j < 64; j++)
            if (p[j]) { if (cnt < 8) g_nbr[row * 8 + cnt] = base + j; cnt++; }
    } else {
        const unsigned int* p = (const unsigned int*)m + row * 64;
        for (int j = 0; j < 64; j++)
            if (p[j]) { if (cnt < 8) g_nbr[row * 8 + cnt] = base + j; cnt++; }
    }
    g_cnt[row] = cnt;
}

// ---------------------------------------------------------------------------
// Weight pre-transform into [chunk][tap][qid][q][nt pad10] uint2 layout
// ---------------------------------------------------------------------------
__global__ void prep_weights(const float* __restrict__ w_x0, const float* __restrict__ w_n0,
                             const float* __restrict__ w_x1, const float* __restrict__ w_n1) {
    int e = blockIdx.x * 256 + threadIdx.x;
    if (e >= WPREP_TOTAL) return;
    int nt = e % 10; int t = e / 10;
    int q   = t & 3;  t >>= 2;
    int qid = t & 7;  t >>= 3;
    int tap = t % 9;  t /= 9;        // t = chunk id 0..31
    int cc   = t & 7;
    int half = (t >> 3) & 1;
    int layer = t >> 4;
    const float* w = layer ? (half ? w_n1 : w_x1) : (half ? w_n0 : w_x0);
    uint2 v = make_uint2(0u, 0u);
    if (nt < 8) {
        int co = nt * 8 + qid;
        int cb = cc * 8;
        v.x = f2tf32(w[co * 576 + (cb + q) * 9 + tap]);
        v.y = f2tf32(w[co * 576 + (cb + q + 4) * 9 + tap]);
    }
    g_wprep[e] = v;
}

// ---------------------------------------------------------------------------
// Neighbor aggregation (unchanged)
// ---------------------------------------------------------------------------
__global__ void agg_kernel(const float* __restrict__ src, float* __restrict__ dst) {
    int node = blockIdx.x;
    int cnt = g_cnt[node];
    if (cnt > 8) cnt = 8;
    int i0 = blockIdx.y * blockDim.x + threadIdx.x;
    int stride = gridDim.y * blockDim.x;
    const float4* s4 = (const float4*)src;
    float4* d4 = (float4*)dst;
    int nb[8];
    for (int k = 0; k < cnt; k++) nb[k] = g_nbr[node * 8 + k];
    const int n4 = IMGSZ / 4;
    for (int i = i0; i < n4; i += stride) {
        float4 acc = make_float4(0.f, 0.f, 0.f, 0.f);
        for (int k = 0; k < cnt; k++) {
            float4 v = s4[nb[k] * n4 + i];
            acc.x += v.x; acc.y += v.y; acc.z += v.z; acc.w += v.w;
        }
        d4[node * n4 + i] = acc;
    }
}

// ---------------------------------------------------------------------------
// Conv: cp.async patch + weights, LDS.128 B-frags, reg-double-buffered taps
// ---------------------------------------------------------------------------
__device__ __forceinline__ void issue_chunk(float* pat, uint4* wdst,
                                            const uint2* __restrict__ wsrc,
                                            const float* __restrict__ inp,
                                            int n, int cb, int y0, int tid) {
    // weights: 1440 uint4 contiguous
    const uint4* ws = (const uint4*)wsrc;
#pragma unroll
    for (int k = 0; k < 6; k++) {
        int idx = tid + k * 256;
        if (idx < W_CHUNK / 2) cp16(wdst + idx, ws + idx);
    }
    // patch: 8c x 10r x 32col fp32, predicated rows (halo stays zero)
#pragma unroll
    for (int k = 0; k < 10; k++) {
        int i = tid + k * 256;
        int col = i & 31;
        int r = (i >> 5) % 10;
        int c = i / 320;
        int gy = y0 + r - 1;
        if (gy >= 0 && gy < HW)
            cp4(pat + c * P_CSTR + r * P_RSTR + 1 + col,
                inp + ((n * CCH + c + cb) * HW + gy) * HW + col);
    }
    asm volatile("cp.async.commit_group;" ::: "memory");
}

__global__ __launch_bounds__(256, 2)
void conv_kernel(const float* __restrict__ inA, const float* __restrict__ inB,
                 const uint2* __restrict__ wprep,   // this layer's 16 chunks
                 const float* __restrict__ bA,  const float* __restrict__ bB,
                 const float* __restrict__ resid, float* __restrict__ out) {
    extern __shared__ uint8_t smem[];
    float* patB[2];
    patB[0] = (float*)smem;
    patB[1] = patB[0] + P_ELEMS;
    uint4* wsmB[2];
    wsmB[0] = (uint4*)(patB[1] + P_ELEMS);
    wsmB[1] = wsmB[0] + W_CHUNK / 2;

    const int n = blockIdx.y;
    const int rb = blockIdx.x;
    const int tid = threadIdx.x;
    const int w = tid >> 5;
    const int lane = tid & 31;
    const int qid = lane >> 2;
    const int q = lane & 3;
    const int y0 = rb * 8;

    // zero both patch buffers once (halo cells never overwritten later)
#pragma unroll
    for (int k = 0; k < 23; k++) {
        int i = tid + k * 256;
        if (i < 2 * P_ELEMS) patB[0][i] = 0.f;
    }
    __syncthreads();

    float acc[2][8][4];
#pragma unroll
    for (int mt = 0; mt < 2; mt++)
#pragma unroll
        for (int nt = 0; nt < 8; nt++)
#pragma unroll
            for (int r = 0; r < 4; r++) acc[mt][nt][r] = 0.f;

    // prolog: chunk 0
    issue_chunk(patB[0], wsmB[0], wprep, inA, n, 0, y0, tid);
    asm volatile("cp.async.wait_group 0;" ::: "memory");
    __syncthreads();

    const int wtbase = (qid * 4 + q) * 5;   // uint4 index within a tap block

    for (int it = 0; it < 16; ++it) {
        const int p = it & 1;
        if (it < 15) {
            const int jt = it + 1;
            issue_chunk(patB[1 - p], wsmB[1 - p], wprep + jt * W_CHUNK,
                        (jt >> 3) ? inB : inA, n, (jt & 7) * 8, y0, tid);
        }

        // compute chunk it
        {
            const float* __restrict__ pat = patB[p];
            const uint4* __restrict__ wq = wsmB[p];

            uint4 bb[2][4];
            // load tap 0 B-frags
#pragma unroll
            for (int j = 0; j < 4; j++) bb[0][j] = wq[wtbase + j];

#pragma unroll
            for (int tap = 0; tap < 9; tap++) {
                const int ty = tap / 3, tx = tap % 3;
                const int cur = tap & 1;
                // prefetch next tap's B-frags (tap block = W_TAP_U4 uint4)
                if (tap < 8) {
                    const uint4* wn = wq + (tap + 1) * W_TAP_U4 + wtbase;
#pragma unroll
                    for (int j = 0; j < 4; j++) bb[1 - cur][j] = wn[j];
                }
                // A fragments for both mt (8 LDS.32 + cvt)
                const int ro = (w + ty) * P_RSTR + qid + tx;
                const int blo = q * P_CSTR + ro;
                const int bhi = (q + 4) * P_CSTR + ro;
                uint32_t a[2][4];
#pragma unroll
                for (int mt = 0; mt < 2; mt++) {
                    const int xo = mt * 16;
                    a[mt][0] = f2tf32(pat[blo + xo]);
                    a[mt][1] = f2tf32(pat[blo + xo + 8]);
                    a[mt][2] = f2tf32(pat[bhi + xo]);
                    a[mt][3] = f2tf32(pat[bhi + xo + 8]);
                }
                const uint32_t* b = (const uint32_t*)bb[cur];
#pragma unroll
                for (int mt = 0; mt < 2; mt++)
#pragma unroll
                    for (int nt = 0; nt < 8; nt++)
                        mma_tf32(acc[mt][nt][0], acc[mt][nt][1],
                                 acc[mt][nt][2], acc[mt][nt][3],
                                 a[mt][0], a[mt][1], a[mt][2], a[mt][3],
                                 b[2 * nt], b[2 * nt + 1]);
            }
        }

        asm volatile("cp.async.wait_group 0;" ::: "memory");
        __syncthreads();
    }

    // epilogue: bias (bA + cnt*bB), optional residual, relu
    const int gy = y0 + w;
    const float cntf = (float)g_cnt[n];
#pragma unroll
    for (int nt = 0; nt < 8; nt++) {
        const int co = nt * 8 + 2 * q;
        const float bias0 = bA[co]     + cntf * bB[co];
        const float bias1 = bA[co + 1] + cntf * bB[co + 1];
#pragma unroll
        for (int mt = 0; mt < 2; mt++) {
            const int xa = mt * 16 + qid;
            const int xc = xa + 8;
            const int o0 = ((n * CCH + co) * HW + gy) * HW;
            float r0 = acc[mt][nt][0] + bias0;
            float r1 = acc[mt][nt][1] + bias1;
            float r2 = acc[mt][nt][2] + bias0;
            float r3 = acc[mt][nt][3] + bias1;
            if (resid) {
                r0 += resid[o0 + xa];
                r1 += resid[o0 + 1024 + xa];
                r2 += resid[o0 + xc];
                r3 += resid[o0 + 1024 + xc];
            }
            out[o0 + xa]        = fmaxf(r0, 0.f);
            out[o0 + 1024 + xa] = fmaxf(r1, 0.f);
            out[o0 + xc]        = fmaxf(r2, 0.f);
            out[o0 + 1024 + xc] = fmaxf(r3, 0.f);
        }
    }
}

// ---------------------------------------------------------------------------
extern "C" void kernel_launch(void* const* d_in, const int* in_sizes, int n_in,
                              void* d_out, int out_size) {
    const float* x    = (const float*)d_in[0];
    const float* w_x0 = (const float*)d_in[1];
    const float* b_x0 = (const float*)d_in[2];
    const float* w_n0 = (const float*)d_in[3];
    const float* b_n0 = (const float*)d_in[4];
    const float* w_x1 = (const float*)d_in[5];
    const float* b_x1 = (const float*)d_in[6];
    const float* w_n1 = (const float*)d_in[7];
    const float* b_n1 = (const float*)d_in[8];
    const void*  msk  = d_in[9];
    float* out = (float*)d_out;

    float *xs, *h, *hs;
    uint2* wprep;
    cudaGetSymbolAddress((void**)&xs, g_xs);
    cudaGetSymbolAddress((void**)&h,  g_h);
    cudaGetSymbolAddress((void**)&hs, g_hs);
    cudaGetSymbolAddress((void**)&wprep, g_wprep);

    static bool attr_set = false;
    if (!attr_set) {
        cudaFuncSetAttribute(conv_kernel, cudaFuncAttributeMaxDynamicSharedMemorySize,
                             SMEM_BYTES);
        attr_set = true;
    }

    detect_kernel<<<1, 256>>>(msk);
    build_kernel<<<1, 256>>>(msk);
    prep_weights<<<(WPREP_TOTAL + 255) / 256, 256>>>(w_x0, w_n0, w_x1, w_n1);

    dim3 agrid(NODES, 16);
    dim3 cgrid(4, NIMG);

    // layer 1
    agg_kernel<<<agrid, 256>>>(x, xs);
    conv_kernel<<<cgrid, 256, SMEM_BYTES>>>(x, xs, wprep, b_x0, b_n0, nullptr, h);

    // layer 2
    agg_kernel<<<agrid, 256>>>(h, hs);
    conv_kernel<<<cgrid, 256, SMEM_BYTES>>>(h, hs, wprep + 16 * W_CHUNK, b_x1, b_n1, x, out);
}